// round 12
// baseline (speedup 1.0000x reference)
#include <cuda_runtime.h>
#include <math.h>
#include <cstdint>
#include <stdint.h>

#define T_TOKENS 4096
#define DMODEL   1024
#define DFFN     4096
#define NEXP     8
#define TOPK     2
#define NSLOTS   (T_TOKENS * TOPK)
#define MT_MAX   64

// ---- scratch (__device__ globals; allocation-free rule) ----
__device__ float g_h[(size_t)NSLOTS * DFFN];        // 128 MiB (tf32-rounded)
__device__ float g_o[(size_t)NSLOTS * DMODEL];      // 32 MiB  per-slot fc2 output
__device__ float g_xr[(size_t)T_TOKENS * DMODEL];   // 16 MiB  (tf32-rounded x)
__device__ int   g_tok[NSLOTS];
__device__ float g_gate[NSLOTS];
__device__ int   g_pos[T_TOKENS * TOPK];            // token -> slot map
__device__ int   g_counts[NEXP];
__device__ int   g_cursor[NEXP];
__device__ int   g_off[NEXP + 1];
__device__ int   g_topi[T_TOKENS * TOPK];
__device__ float g_topg[T_TOKENS * TOPK];
__device__ int   g_done;

// ---------------------------------------------------------------------------
__device__ __forceinline__ uint32_t smem_u32(const void* p) {
    uint32_t a;
    asm("{ .reg .u64 t; cvta.to.shared.u64 t, %1; cvt.u32.u64 %0, t; }" : "=r"(a) : "l"(p));
    return a;
}
__device__ __forceinline__ void cp_async16u(uint32_t daddr, const float* src) {
    asm volatile("cp.async.cg.shared.global [%0], [%1], 16;\n" :: "r"(daddr), "l"(src));
}
#define CP_COMMIT() asm volatile("cp.async.commit_group;\n" ::: "memory")

__device__ __forceinline__ float round_tf32(float f) {
    uint32_t r;
    asm("cvt.rna.tf32.f32 %0, %1;" : "=r"(r) : "f"(f));
    return __uint_as_float(r);
}
__device__ __forceinline__ uint32_t f2tf32u(float f) {
    uint32_t r;
    asm("cvt.rna.tf32.f32 %0, %1;" : "=r"(r) : "f"(f));
    return r;
}

// ---------------------------------------------------------------------------
// One warp per token: noisy top-2 router. Also writes tf32-rounded x to g_xr.
// Last block computes expert offsets.
__global__ void router_kernel(const float* __restrict__ x, const float* __restrict__ noise,
                              const float* __restrict__ Wg, const float* __restrict__ bg,
                              const float* __restrict__ Wn, const float* __restrict__ bn) {
    int gw = (blockIdx.x * blockDim.x + threadIdx.x) >> 5;
    int lane = threadIdx.x & 31;
    if (gw < T_TOKENS) {
        const float* xr = x + (size_t)gw * DMODEL;
        float* xo = g_xr + (size_t)gw * DMODEL;
        float lg[NEXP], ln[NEXP];
#pragma unroll
        for (int e = 0; e < NEXP; e++) { lg[e] = 0.f; ln[e] = 0.f; }
        for (int d = lane; d < DMODEL; d += 32) {
            float xv = xr[d];
            xo[d] = round_tf32(xv);             // fused tf32 pre-round of x
#pragma unroll
            for (int e = 0; e < NEXP; e++) {
                lg[e] += xv * Wg[d * NEXP + e];
                ln[e] += xv * Wn[d * NEXP + e];
            }
        }
#pragma unroll
        for (int o = 16; o > 0; o >>= 1) {
#pragma unroll
            for (int e = 0; e < NEXP; e++) {
                lg[e] += __shfl_xor_sync(0xffffffffu, lg[e], o);
                ln[e] += __shfl_xor_sync(0xffffffffu, ln[e], o);
            }
        }
        if (lane == 0) {
            float nv[NEXP];
#pragma unroll
            for (int e = 0; e < NEXP; e++) {
                float nl = ln[e] + bn[e];
                float sp = (nl > 20.f) ? nl : log1pf(expf(nl));
                nv[e] = lg[e] + bg[e] + noise[gw * NEXP + e] * sp;
            }
            int i0 = 0;
#pragma unroll
            for (int e = 1; e < NEXP; e++) if (nv[e] > nv[i0]) i0 = e;
            int i1 = (i0 == 0) ? 1 : 0;
#pragma unroll
            for (int e = 0; e < NEXP; e++) if (e != i0 && nv[e] > nv[i1]) i1 = e;
            float e1 = expf(nv[i1] - nv[i0]);
            float s = 1.f + e1;
            g_topi[gw * 2]     = i0;  g_topg[gw * 2]     = 1.f / s;
            g_topi[gw * 2 + 1] = i1;  g_topg[gw * 2 + 1] = e1 / s;
            atomicAdd(&g_counts[i0], 1);
            atomicAdd(&g_counts[i1], 1);
        }
    }
    __syncthreads();
    if (threadIdx.x == 0) {
        __threadfence();
        int prev = atomicAdd(&g_done, 1);
        if (prev == (int)gridDim.x - 1) {
            g_done = 0;
            __threadfence();
            int acc = 0;
            for (int e = 0; e < NEXP; e++) {
                g_off[e] = acc; g_cursor[e] = acc;
                acc += g_counts[e];
                g_counts[e] = 0;        // ready for next replay
            }
            g_off[NEXP] = acc;
        }
    }
}

__global__ void scatter_kernel() {
    int t = blockIdx.x * blockDim.x + threadIdx.x;
    if (t >= T_TOKENS) return;
#pragma unroll
    for (int k = 0; k < TOPK; k++) {
        int e = g_topi[t * 2 + k];
        int pos = atomicAdd(&g_cursor[e], 1);
        g_tok[pos]  = t;
        g_gate[pos] = g_topg[t * 2 + k];
        g_pos[t * 2 + k] = pos;
    }
}

// out[t] = g_o[slot0] + g_o[slot1]  (vectorized float4)
__global__ void combine_kernel(float4* __restrict__ out) {
    int idx = blockIdx.x * blockDim.x + threadIdx.x;     // over T_TOKENS*256 float4s
    int t  = idx >> 8;
    int d4 = idx & 255;
    const float4* r0 = (const float4*)(g_o + (size_t)g_pos[t * 2]     * DMODEL) + d4;
    const float4* r1 = (const float4*)(g_o + (size_t)g_pos[t * 2 + 1] * DMODEL) + d4;
    float4 a = *r0, b = *r1;
    a.x += b.x; a.y += b.y; a.z += b.z; a.w += b.w;
    out[idx] = a;
}

// ---------------------------------------------------------------------------
// Grouped GEMM: mma.sync.m16n8k8 tf32.
//   8 warps, warp tile 32x64, CTA tile 128x128x32, NSTG=3 cp.async ring.
//   Forced 2 CTAs/SM (regs<=128) -> 16 warps/SM = 4 warps/SMSP.
//   PHASE 0: g_h = relu(gather(xr) @ W1 + b1)       K=1024
//   PHASE 1: g_o[slot] = gate * (g_h @ W2 + b2)     K=4096 (plain stores)
#define BM 128
#define BN 128
#define BK 32
#define NSTG 3
#define NTHREADS 256
#define LDB 136                               // floats; conflict-free B reads
#define A_BYTES   (BM * 128)                  // 16384 (128B swizzled rows)
#define B_BYTES   (BK * LDB * 4)              // 17408
#define STG_BYTES (A_BYTES + B_BYTES)         // 33792
#define SMEM_BIAS (NSTG * STG_BYTES)
#define SMEM_TOTAL (SMEM_BIAS + BN * 4)       // 101888 -> 2 CTAs/SM

__device__ __forceinline__ void mma_tf32(float* c, const uint32_t* a, const uint32_t* b) {
    asm volatile(
        "mma.sync.aligned.m16n8k8.row.col.f32.tf32.tf32.f32 "
        "{%0,%1,%2,%3}, {%4,%5,%6,%7}, {%8,%9}, {%0,%1,%2,%3};"
        : "+f"(c[0]), "+f"(c[1]), "+f"(c[2]), "+f"(c[3])
        : "r"(a[0]), "r"(a[1]), "r"(a[2]), "r"(a[3]), "r"(b[0]), "r"(b[1]));
}
__device__ __forceinline__ void ldsm_x4(uint32_t* r, uint32_t addr) {
    asm volatile("ldmatrix.sync.aligned.m8n8.x4.shared.b16 {%0,%1,%2,%3}, [%4];"
                 : "=r"(r[0]), "=r"(r[1]), "=r"(r[2]), "=r"(r[3]) : "r"(addr));
}

template <int PHASE>
__global__ __launch_bounds__(NTHREADS, 2)
void moe_gemm_mma(const float* __restrict__ W1, const float* __restrict__ b1,
                  const float* __restrict__ W2, const float* __restrict__ b2) {
    constexpr int K  = PHASE ? DFFN : DMODEL;
    constexpr int NN = PHASE ? DMODEL : DFFN;

    int e  = blockIdx.x >> 6;
    int mt = blockIdx.x & (MT_MAX - 1);
    int off0  = g_off[e];
    int count = g_off[e + 1] - off0;
    if (mt * BM >= count) return;
    int n0 = blockIdx.y * BN;

    extern __shared__ char smem[];
    uint32_t sb = smem_u32(smem);
    float* sBias = (float*)(smem + SMEM_BIAS);

    int tid  = threadIdx.x;
    int wid  = tid >> 5;
    int lane = tid & 31;
    int wm = wid & 3;              // 4 warps along M (32 rows each)
    int wn = wid >> 2;             // 2 warps along N (64 cols each)

    const float* bias = PHASE ? (b2 + e * DMODEL) : (b1 + e * DFFN);
    if (tid < BN) sBias[tid] = bias[n0 + tid];

    const float* Bsrc = PHASE ? (W2 + (size_t)e * DFFN * DMODEL)
                              : (W1 + (size_t)e * DMODEL * DFFN);

    // ---- per-thread cp.async assignments (256 threads) ----
    int ac = tid & 7;
    const float* aP[4];
    uint32_t aDst[4];
#pragma unroll
    for (int i = 0; i < 4; i++) {
        int idx = tid + i * NTHREADS;
        int row = idx >> 3;
        int lr = mt * BM + row;
        if (lr >= count) lr = count - 1;
        int slot = off0 + lr;
        const float* base = PHASE ? (g_h + (size_t)slot * DFFN)
                                  : (g_xr + (size_t)g_tok[slot] * DMODEL);
        aP[i]  = base + ac * 4;
        aDst[i] = (uint32_t)(row * 128 + ((ac ^ (row & 7)) << 4));
    }

    const int nIter = K / BK;

    auto prefetch = [&](int s, int k0) {
        uint32_t ab = sb + s * STG_BYTES;
        uint32_t bb = ab + A_BYTES;
#pragma unroll
        for (int i = 0; i < 4; i++)
            cp_async16u(ab + aDst[i], aP[i] + k0);
#pragma unroll
        for (int i = 0; i < 4; i++) {            // B: 32 k-rows x 32 chunks
            int idx = tid + i * NTHREADS;
            int kr = idx >> 5, c = idx & 31;
            cp_async16u(bb + (uint32_t)(kr * (LDB * 4) + c * 16),
                        Bsrc + (size_t)(k0 + kr) * NN + n0 + c * 4);
        }
    };

#pragma unroll
    for (int p = 0; p < NSTG; p++) { prefetch(p, p * BK); CP_COMMIT(); }

    float acc[2][8][4];
#pragma unroll
    for (int mi = 0; mi < 2; mi++)
#pragma unroll
        for (int nj = 0; nj < 8; nj++)
#pragma unroll
            for (int r = 0; r < 4; r++) acc[mi][nj][r] = 0.f;

    // per-lane fragment address components
    int lrow = (lane & 7) + (((lane >> 3) & 1) << 3);   // 0..15
    int lchv = lane >> 4;                                // chunk parity
    int btg  = lane & 3;                                 // B k within quad
    int bgq  = lane >> 2;                                // B n within n8

    for (int i = 0; i < nIter; i++) {
        int rem = nIter - 1 - i;
        if (rem >= NSTG - 1)      asm volatile("cp.async.wait_group 2;\n" ::: "memory");
        else if (rem == 1)        asm volatile("cp.async.wait_group 1;\n" ::: "memory");
        else                      asm volatile("cp.async.wait_group 0;\n" ::: "memory");
        __syncthreads();
        int s = i % NSTG;
        uint32_t aBase = sb + s * STG_BYTES;
        const float* Bs = (const float*)(smem + s * STG_BYTES + A_BYTES);

#pragma unroll
        for (int ks = 0; ks < 4; ks++) {
            uint32_t ra[2][4];
#pragma unroll
            for (int mi = 0; mi < 2; mi++) {
                int row = wm * 32 + mi * 16 + lrow;
                int chunk = 2 * ks + lchv;
                uint32_t addr = aBase + (uint32_t)(row * 128 + ((chunk ^ (row & 7)) << 4));
                ldsm_x4(ra[mi], addr);
            }
            uint32_t rb[8][2];
            const float* bp = Bs + (ks * 8 + btg) * LDB + wn * 64 + bgq;
#pragma unroll
            for (int nj = 0; nj < 8; nj++) {
                rb[nj][0] = f2tf32u(bp[nj * 8]);
                rb[nj][1] = f2tf32u(bp[nj * 8 + 4 * LDB]);
            }
#pragma unroll
            for (int mi = 0; mi < 2; mi++)
#pragma unroll
                for (int nj = 0; nj < 8; nj++)
                    mma_tf32(acc[mi][nj], ra[mi], rb[nj]);
        }
        __syncthreads();
        if (i + NSTG < nIter) { prefetch(s, (i + NSTG) * BK); CP_COMMIT(); }
    }

    // ---- epilogue straight from registers (plain stores both phases) ----
    int g  = lane >> 2;
    int tg = lane & 3;
#pragma unroll
    for (int mi = 0; mi < 2; mi++) {
#pragma unroll
        for (int half = 0; half < 2; half++) {
            int lr = mt * BM + wm * 32 + mi * 16 + half * 8 + g;
            if (lr >= count) continue;
            int slot = off0 + lr;
            if (PHASE == 0) {
                float* hrow = g_h + (size_t)slot * DFFN + n0;
#pragma unroll
                for (int nj = 0; nj < 8; nj++) {
                    int cl = wn * 64 + nj * 8 + tg * 2;
                    float2 v;
                    v.x = round_tf32(fmaxf(acc[mi][nj][half * 2 + 0] + sBias[cl],     0.f));
                    v.y = round_tf32(fmaxf(acc[mi][nj][half * 2 + 1] + sBias[cl + 1], 0.f));
                    *(float2*)(hrow + cl) = v;
                }
            } else {
                float gate = g_gate[slot];
                float* orow = g_o + (size_t)slot * DMODEL + n0;
#pragma unroll
                for (int nj = 0; nj < 8; nj++) {
                    int cl = wn * 64 + nj * 8 + tg * 2;
                    float2 v;
                    v.x = (acc[mi][nj][half * 2 + 0] + sBias[cl])     * gate;
                    v.y = (acc[mi][nj][half * 2 + 1] + sBias[cl + 1]) * gate;
                    *(float2*)(orow + cl) = v;
                }
            }
        }
    }
}

// ---------------------------------------------------------------------------
extern "C" void kernel_launch(void* const* d_in, const int* in_sizes, int n_in,
                              void* d_out, int out_size) {
    const float* x     = (const float*)d_in[0];
    const float* noise = (const float*)d_in[1];
    const float* Wg    = (const float*)d_in[2];
    const float* bg    = (const float*)d_in[3];
    const float* Wn    = (const float*)d_in[4];
    const float* bn    = (const float*)d_in[5];
    const float* W1    = (const float*)d_in[6];
    const float* b1    = (const float*)d_in[7];
    const float* W2    = (const float*)d_in[8];
    const float* b2    = (const float*)d_in[9];
    float* out = (float*)d_out;

    cudaFuncSetAttribute(moe_gemm_mma<0>, cudaFuncAttributeMaxDynamicSharedMemorySize, SMEM_TOTAL);
    cudaFuncSetAttribute(moe_gemm_mma<1>, cudaFuncAttributeMaxDynamicSharedMemorySize, SMEM_TOTAL);

    router_kernel<<<(T_TOKENS * 32) / 256, 256>>>(x, noise, Wg, bg, Wn, bn);   // 1 (+x round, +offsets)
    scatter_kernel<<<T_TOKENS / 256, 256>>>();                                 // 2 (+g_pos)
    moe_gemm_mma<0><<<dim3(NEXP * MT_MAX, DFFN / BN), NTHREADS, SMEM_TOTAL>>>(W1, b1, W2, b2);   // 3
    moe_gemm_mma<1><<<dim3(NEXP * MT_MAX, DMODEL / BN), NTHREADS, SMEM_TOTAL>>>(W1, b1, W2, b2); // 4
    combine_kernel<<<(T_TOKENS * 256) / 256, 256>>>((float4*)out);             // 5
}

// round 13
// speedup vs baseline: 1.8234x; 1.8234x over previous
#include <cuda_runtime.h>
#include <cuda_fp16.h>
#include <math.h>
#include <cstdint>
#include <stdint.h>

#define T_TOKENS 4096
#define DMODEL   1024
#define DFFN     4096
#define NEXP     8
#define TOPK     2
#define NSLOTS   (T_TOKENS * TOPK)
#define MT_MAX   32

// ---- scratch (__device__ globals; allocation-free rule) ----
__device__ __half g_hh[(size_t)NSLOTS * DFFN];        // 64 MiB fp16 activations
__device__ __half g_xh[(size_t)T_TOKENS * DMODEL];    // 8 MiB  fp16 x
__device__ __half g_w1h[(size_t)NEXP * DMODEL * DFFN];// 64 MiB fp16 W1
__device__ __half g_w2h[(size_t)NEXP * DFFN * DMODEL];// 64 MiB fp16 W2
__device__ float  g_o[(size_t)NSLOTS * DMODEL];       // 32 MiB per-slot fc2 output
__device__ int    g_tok[NSLOTS];
__device__ float  g_gate[NSLOTS];
__device__ int    g_pos[T_TOKENS * TOPK];
__device__ int    g_counts[NEXP];
__device__ int    g_cursor[NEXP];
__device__ int    g_off[NEXP + 1];
__device__ int    g_topi[T_TOKENS * TOPK];
__device__ float  g_topg[T_TOKENS * TOPK];
__device__ int    g_done;

// ---------------------------------------------------------------------------
__device__ __forceinline__ uint32_t smem_u32(const void* p) {
    uint32_t a;
    asm("{ .reg .u64 t; cvta.to.shared.u64 t, %1; cvt.u32.u64 %0, t; }" : "=r"(a) : "l"(p));
    return a;
}
__device__ __forceinline__ void cp_async16u(uint32_t daddr, const void* src) {
    asm volatile("cp.async.cg.shared.global [%0], [%1], 16;\n" :: "r"(daddr), "l"(src));
}
#define CP_COMMIT() asm volatile("cp.async.commit_group;\n" ::: "memory")

// ---------------------------------------------------------------------------
// W1/W2 -> fp16 scratch (one streamed pass)
#define W_F4 8388608      // NEXP*DMODEL*DFFN / 4
__global__ void convert_w(const float4* __restrict__ W1, const float4* __restrict__ W2) {
    uint2* d1 = (uint2*)g_w1h;
    uint2* d2 = (uint2*)g_w2h;
    int stride = gridDim.x * blockDim.x;
    for (int i = blockIdx.x * blockDim.x + threadIdx.x; i < 2 * W_F4; i += stride) {
        float4 v = (i < W_F4) ? W1[i] : W2[i - W_F4];
        __half2 h0 = __float22half2_rn(make_float2(v.x, v.y));
        __half2 h1 = __float22half2_rn(make_float2(v.z, v.w));
        uint2 u;
        u.x = *reinterpret_cast<uint32_t*>(&h0);
        u.y = *reinterpret_cast<uint32_t*>(&h1);
        if (i < W_F4) d1[i] = u; else d2[i - W_F4] = u;
    }
}

// One warp per token: noisy top-2 router. Also writes fp16 x to g_xh.
// Last block computes expert offsets.
__global__ void router_kernel(const float* __restrict__ x, const float* __restrict__ noise,
                              const float* __restrict__ Wg, const float* __restrict__ bg,
                              const float* __restrict__ Wn, const float* __restrict__ bn) {
    int gw = (blockIdx.x * blockDim.x + threadIdx.x) >> 5;
    int lane = threadIdx.x & 31;
    if (gw < T_TOKENS) {
        const float* xr = x + (size_t)gw * DMODEL;
        __half* xo = g_xh + (size_t)gw * DMODEL;
        float lg[NEXP], ln[NEXP];
#pragma unroll
        for (int e = 0; e < NEXP; e++) { lg[e] = 0.f; ln[e] = 0.f; }
        for (int d = lane; d < DMODEL; d += 32) {
            float xv = xr[d];
            xo[d] = __float2half_rn(xv);        // fused fp16 quantization of x
#pragma unroll
            for (int e = 0; e < NEXP; e++) {
                lg[e] += xv * Wg[d * NEXP + e];
                ln[e] += xv * Wn[d * NEXP + e];
            }
        }
#pragma unroll
        for (int o = 16; o > 0; o >>= 1) {
#pragma unroll
            for (int e = 0; e < NEXP; e++) {
                lg[e] += __shfl_xor_sync(0xffffffffu, lg[e], o);
                ln[e] += __shfl_xor_sync(0xffffffffu, ln[e], o);
            }
        }
        if (lane == 0) {
            float nv[NEXP];
#pragma unroll
            for (int e = 0; e < NEXP; e++) {
                float nl = ln[e] + bn[e];
                float sp = (nl > 20.f) ? nl : log1pf(expf(nl));
                nv[e] = lg[e] + bg[e] + noise[gw * NEXP + e] * sp;
            }
            int i0 = 0;
#pragma unroll
            for (int e = 1; e < NEXP; e++) if (nv[e] > nv[i0]) i0 = e;
            int i1 = (i0 == 0) ? 1 : 0;
#pragma unroll
            for (int e = 0; e < NEXP; e++) if (e != i0 && nv[e] > nv[i1]) i1 = e;
            float e1 = expf(nv[i1] - nv[i0]);
            float s = 1.f + e1;
            g_topi[gw * 2]     = i0;  g_topg[gw * 2]     = 1.f / s;
            g_topi[gw * 2 + 1] = i1;  g_topg[gw * 2 + 1] = e1 / s;
            atomicAdd(&g_counts[i0], 1);
            atomicAdd(&g_counts[i1], 1);
        }
    }
    __syncthreads();
    if (threadIdx.x == 0) {
        __threadfence();
        int prev = atomicAdd(&g_done, 1);
        if (prev == (int)gridDim.x - 1) {
            g_done = 0;
            __threadfence();
            int acc = 0;
            for (int e = 0; e < NEXP; e++) {
                g_off[e] = acc; g_cursor[e] = acc;
                acc += g_counts[e];
                g_counts[e] = 0;        // ready for next replay
            }
            g_off[NEXP] = acc;
        }
    }
}

__global__ void scatter_kernel() {
    int t = blockIdx.x * blockDim.x + threadIdx.x;
    if (t >= T_TOKENS) return;
#pragma unroll
    for (int k = 0; k < TOPK; k++) {
        int e = g_topi[t * 2 + k];
        int pos = atomicAdd(&g_cursor[e], 1);
        g_tok[pos]  = t;
        g_gate[pos] = g_topg[t * 2 + k];
        g_pos[t * 2 + k] = pos;
    }
}

// out[t] = g_o[slot0] + g_o[slot1]
__global__ void combine_kernel(float4* __restrict__ out) {
    int idx = blockIdx.x * blockDim.x + threadIdx.x;
    int t  = idx >> 8;
    int d4 = idx & 255;
    const float4* r0 = (const float4*)(g_o + (size_t)g_pos[t * 2]     * DMODEL) + d4;
    const float4* r1 = (const float4*)(g_o + (size_t)g_pos[t * 2 + 1] * DMODEL) + d4;
    float4 a = *r0, b = *r1;
    a.x += b.x; a.y += b.y; a.z += b.z; a.w += b.w;
    out[idx] = a;
}

// ---------------------------------------------------------------------------
// Grouped GEMM: mma.sync.m16n8k16 fp16 (f32 accum), all-ldmatrix operands.
//   4 warps, warp tile 64x64, CTA tile 128x128x64, NSTG=3 cp.async ring.
//   PHASE 0: g_hh = fp16(relu(gather(g_xh) @ W1h + b1))   K=1024 (16 iters)
//   PHASE 1: g_o[slot] = gate * (g_hh @ W2h + b2)         K=4096 (64 iters)
#define BM 128
#define BN 128
#define BK 64
#define NSTG 3
#define A_BYTES   (BM * 128)                  // 16384: 128 rows x 64 halves (128B, XOR swizzle)
#define B_BYTES   (BK * 256)                  // 16384: 64 k-rows x 128 halves (256B, XOR swizzle)
#define STG_BYTES (A_BYTES + B_BYTES)         // 32768
#define SMEM_BIAS (NSTG * STG_BYTES)
#define SMEM_TOTAL (SMEM_BIAS + BN * 4)       // 98816 -> 2 CTAs/SM

__device__ __forceinline__ void mma_f16(float* c, const uint32_t* a, const uint32_t* b) {
    asm volatile(
        "mma.sync.aligned.m16n8k16.row.col.f32.f16.f16.f32 "
        "{%0,%1,%2,%3}, {%4,%5,%6,%7}, {%8,%9}, {%0,%1,%2,%3};"
        : "+f"(c[0]), "+f"(c[1]), "+f"(c[2]), "+f"(c[3])
        : "r"(a[0]), "r"(a[1]), "r"(a[2]), "r"(a[3]), "r"(b[0]), "r"(b[1]));
}
__device__ __forceinline__ void ldsm_x4(uint32_t* r, uint32_t addr) {
    asm volatile("ldmatrix.sync.aligned.m8n8.x4.shared.b16 {%0,%1,%2,%3}, [%4];"
                 : "=r"(r[0]), "=r"(r[1]), "=r"(r[2]), "=r"(r[3]) : "r"(addr));
}
__device__ __forceinline__ void ldsm_x4_t(uint32_t* r, uint32_t addr) {
    asm volatile("ldmatrix.sync.aligned.m8n8.x4.trans.shared.b16 {%0,%1,%2,%3}, [%4];"
                 : "=r"(r[0]), "=r"(r[1]), "=r"(r[2]), "=r"(r[3]) : "r"(addr));
}

template <int PHASE>
__global__ __launch_bounds__(128, 2)
void moe_gemm_mma(const float* __restrict__ b1, const float* __restrict__ b2) {
    constexpr int K  = PHASE ? DFFN : DMODEL;
    constexpr int NN = PHASE ? DMODEL : DFFN;

    int e  = blockIdx.x >> 5;
    int mt = blockIdx.x & (MT_MAX - 1);
    int off0  = g_off[e];
    int count = g_off[e + 1] - off0;
    if (mt * BM >= count) return;
    int n0 = blockIdx.y * BN;

    extern __shared__ char smem[];
    uint32_t sb = smem_u32(smem);
    float* sBias = (float*)(smem + SMEM_BIAS);

    int tid  = threadIdx.x;
    int wid  = tid >> 5;
    int lane = tid & 31;
    int wm = wid & 1;              // 2 warps along M (64 rows)
    int wn = wid >> 1;             // 2 warps along N (64 cols)

    const float* bias = PHASE ? (b2 + e * DMODEL) : (b1 + e * DFFN);
    sBias[tid] = bias[n0 + tid];   // blockDim == BN == 128

    const __half* Bsrc = PHASE ? (g_w2h + (size_t)e * DFFN * DMODEL)
                               : (g_w1h + (size_t)e * DMODEL * DFFN);

    // ---- per-thread cp.async assignments (128 threads) ----
    // A: 128 rows x 8 chunks(16B=8 halves): off = row*128 + ((c ^ (row&7))<<4)
    int ac = tid & 7;
    const __half* aP[8];
    uint32_t aDst[8];
#pragma unroll
    for (int i = 0; i < 8; i++) {
        int idx = tid + i * 128;
        int row = idx >> 3;
        int lr = mt * BM + row;
        if (lr >= count) lr = count - 1;
        int slot = off0 + lr;
        const __half* base = PHASE ? (g_hh + (size_t)slot * DFFN)
                                   : (g_xh + (size_t)g_tok[slot] * DMODEL);
        aP[i]  = base + ac * 8;
        aDst[i] = (uint32_t)(row * 128 + ((ac ^ (row & 7)) << 4));
    }

    const int nIter = K / BK;

    auto prefetch = [&](int s, int k0) {
        uint32_t ab = sb + s * STG_BYTES;
        uint32_t bb = ab + A_BYTES;
#pragma unroll
        for (int i = 0; i < 8; i++)
            cp_async16u(ab + aDst[i], aP[i] + k0);
#pragma unroll
        for (int i = 0; i < 8; i++) {   // B: 64 k-rows x 16 chunks(16B=8 halves)
            int idx = tid + i * 128;
            int kr = idx >> 4, cn = idx & 15;
            cp_async16u(bb + (uint32_t)(kr * 256 + ((cn ^ (kr & 7)) << 4)),
                        Bsrc + (size_t)(k0 + kr) * NN + n0 + cn * 8);
        }
    };

#pragma unroll
    for (int p = 0; p < NSTG; p++) { prefetch(p, p * BK); CP_COMMIT(); }

    float acc[4][8][4];
#pragma unroll
    for (int mi = 0; mi < 4; mi++)
#pragma unroll
        for (int nj = 0; nj < 8; nj++)
#pragma unroll
            for (int r = 0; r < 4; r++) acc[mi][nj][r] = 0.f;

    // per-lane ldmatrix address components
    int lrow = (lane & 7) + (((lane >> 3) & 1) << 3);   // 0..15
    int lhi  = lane >> 4;                                // 0/1 (second chunk / n+8)

    for (int i = 0; i < nIter; i++) {
        int rem = nIter - 1 - i;
        if (rem >= NSTG - 1)      asm volatile("cp.async.wait_group 2;\n" ::: "memory");
        else if (rem == 1)        asm volatile("cp.async.wait_group 1;\n" ::: "memory");
        else                      asm volatile("cp.async.wait_group 0;\n" ::: "memory");
        __syncthreads();
        int s = i % NSTG;
        uint32_t aBase = sb + s * STG_BYTES;
        uint32_t bBase = aBase + A_BYTES;

#pragma unroll
        for (int ks = 0; ks < 4; ks++) {       // 4 x k16
            // A fragments: 4 m16 blocks
            uint32_t ra[4][4];
#pragma unroll
            for (int mi = 0; mi < 4; mi++) {
                int row = wm * 64 + mi * 16 + lrow;
                int chunk = 2 * ks + lhi;
                uint32_t addr = aBase + (uint32_t)(row * 128 + ((chunk ^ (row & 7)) << 4));
                ldsm_x4(ra[mi], addr);
            }
            // B fragments: 4 n16 blocks via ldmatrix.trans
            uint32_t rbq[4][4];
#pragma unroll
            for (int nb = 0; nb < 4; nb++) {
                int kr = ks * 16 + lrow;                 // k-row within BK
                int cn = wn * 8 + nb * 2 + lhi;          // 16B chunk (8 halves of n)
                uint32_t addr = bBase + (uint32_t)(kr * 256 + ((cn ^ (kr & 7)) << 4));
                ldsm_x4_t(rbq[nb], addr);
            }
#pragma unroll
            for (int mi = 0; mi < 4; mi++)
#pragma unroll
                for (int nj = 0; nj < 8; nj++)
                    mma_f16(acc[mi][nj], ra[mi], &rbq[nj >> 1][(nj & 1) * 2]);
        }
        __syncthreads();
        if (i + NSTG < nIter) { prefetch(s, (i + NSTG) * BK); CP_COMMIT(); }
    }

    // ---- epilogue straight from registers ----
    int g  = lane >> 2;
    int tg = lane & 3;
#pragma unroll
    for (int mi = 0; mi < 4; mi++) {
#pragma unroll
        for (int half = 0; half < 2; half++) {
            int lr = mt * BM + wm * 64 + mi * 16 + half * 8 + g;
            if (lr >= count) continue;
            int slot = off0 + lr;
            if (PHASE == 0) {
                __half* hrow = g_hh + (size_t)slot * DFFN + n0;
#pragma unroll
                for (int nj = 0; nj < 8; nj++) {
                    int cl = wn * 64 + nj * 8 + tg * 2;
                    float vx = fmaxf(acc[mi][nj][half * 2 + 0] + sBias[cl],     0.f);
                    float vy = fmaxf(acc[mi][nj][half * 2 + 1] + sBias[cl + 1], 0.f);
                    __half2 h = __float22half2_rn(make_float2(vx, vy));
                    *reinterpret_cast<uint32_t*>(hrow + cl) = *reinterpret_cast<uint32_t*>(&h);
                }
            } else {
                float gate = g_gate[slot];
                float* orow = g_o + (size_t)slot * DMODEL + n0;
#pragma unroll
                for (int nj = 0; nj < 8; nj++) {
                    int cl = wn * 64 + nj * 8 + tg * 2;
                    float2 v;
                    v.x = (acc[mi][nj][half * 2 + 0] + sBias[cl])     * gate;
                    v.y = (acc[mi][nj][half * 2 + 1] + sBias[cl + 1]) * gate;
                    *(float2*)(orow + cl) = v;
                }
            }
        }
    }
}

// ---------------------------------------------------------------------------
extern "C" void kernel_launch(void* const* d_in, const int* in_sizes, int n_in,
                              void* d_out, int out_size) {
    const float* x     = (const float*)d_in[0];
    const float* noise = (const float*)d_in[1];
    const float* Wg    = (const float*)d_in[2];
    const float* bg    = (const float*)d_in[3];
    const float* Wn    = (const float*)d_in[4];
    const float* bn    = (const float*)d_in[5];
    const float* W1    = (const float*)d_in[6];
    const float* b1    = (const float*)d_in[7];
    const float* W2    = (const float*)d_in[8];
    const float* b2    = (const float*)d_in[9];
    float* out = (float*)d_out;

    cudaFuncSetAttribute(moe_gemm_mma<0>, cudaFuncAttributeMaxDynamicSharedMemorySize, SMEM_TOTAL);
    cudaFuncSetAttribute(moe_gemm_mma<1>, cudaFuncAttributeMaxDynamicSharedMemorySize, SMEM_TOTAL);

    convert_w<<<2048, 256>>>((const float4*)W1, (const float4*)W2);            // 1
    router_kernel<<<(T_TOKENS * 32) / 256, 256>>>(x, noise, Wg, bg, Wn, bn);   // 2 (+x fp16, +offsets)
    scatter_kernel<<<T_TOKENS / 256, 256>>>();                                 // 3 (+g_pos)
    moe_gemm_mma<0><<<dim3(NEXP * MT_MAX, DFFN / BN), 128, SMEM_TOTAL>>>(b1, b2);   // 4
    moe_gemm_mma<1><<<dim3(NEXP * MT_MAX, DMODEL / BN), 128, SMEM_TOTAL>>>(b1, b2); // 5
    combine_kernel<<<(T_TOKENS * 256) / 256, 256>>>((float4*)out);             // 6
}

// round 14
// speedup vs baseline: 1.8983x; 1.0410x over previous
#include <cuda_runtime.h>
#include <cuda_fp16.h>
#include <math.h>
#include <cstdint>
#include <stdint.h>

#define T_TOKENS 4096
#define DMODEL   1024
#define DFFN     4096
#define NEXP     8
#define TOPK     2
#define NSLOTS   (T_TOKENS * TOPK)
#define MT_MAX   32

// ---- scratch (__device__ globals; allocation-free rule) ----
__device__ __half g_hh[(size_t)NSLOTS * DFFN];        // 64 MiB fp16 activations
__device__ __half g_xh[(size_t)T_TOKENS * DMODEL];    // 8 MiB  fp16 x
__device__ __half g_w1h[(size_t)NEXP * DMODEL * DFFN];// 64 MiB fp16 W1
__device__ __half g_w2h[(size_t)NEXP * DFFN * DMODEL];// 64 MiB fp16 W2
__device__ float  g_o[(size_t)NSLOTS * DMODEL];       // 32 MiB per-slot fc2 output
__device__ int    g_tok[NSLOTS];
__device__ float  g_gate[NSLOTS];
__device__ int    g_pos[T_TOKENS * TOPK];
__device__ int    g_counts[NEXP];
__device__ int    g_cursor[NEXP];
__device__ int    g_off[NEXP + 1];
__device__ int    g_topi[T_TOKENS * TOPK];
__device__ float  g_topg[T_TOKENS * TOPK];
__device__ int    g_done;

// ---------------------------------------------------------------------------
__device__ __forceinline__ uint32_t smem_u32(const void* p) {
    uint32_t a;
    asm("{ .reg .u64 t; cvta.to.shared.u64 t, %1; cvt.u32.u64 %0, t; }" : "=r"(a) : "l"(p));
    return a;
}
__device__ __forceinline__ void cp_async16u(uint32_t daddr, const void* src) {
    asm volatile("cp.async.cg.shared.global [%0], [%1], 16;\n" :: "r"(daddr), "l"(src));
}
#define CP_COMMIT() asm volatile("cp.async.commit_group;\n" ::: "memory")

// ---------------------------------------------------------------------------
// W (f32) -> fp16 scratch, one weight tensor per launch
#define W_F4 8388608      // NEXP*DMODEL*DFFN / 4
__global__ void convert_w(const float4* __restrict__ W, uint2* __restrict__ dst) {
    int stride = gridDim.x * blockDim.x;
    for (int i = blockIdx.x * blockDim.x + threadIdx.x; i < W_F4; i += stride) {
        float4 v = W[i];
        __half2 h0 = __float22half2_rn(make_float2(v.x, v.y));
        __half2 h1 = __float22half2_rn(make_float2(v.z, v.w));
        uint2 u;
        u.x = *reinterpret_cast<uint32_t*>(&h0);
        u.y = *reinterpret_cast<uint32_t*>(&h1);
        dst[i] = u;
    }
}

// One warp per token: noisy top-2 router. Also writes fp16 x to g_xh.
// Last block computes expert offsets.
__global__ void router_kernel(const float* __restrict__ x, const float* __restrict__ noise,
                              const float* __restrict__ Wg, const float* __restrict__ bg,
                              const float* __restrict__ Wn, const float* __restrict__ bn) {
    int gw = (blockIdx.x * blockDim.x + threadIdx.x) >> 5;
    int lane = threadIdx.x & 31;
    if (gw < T_TOKENS) {
        const float* xr = x + (size_t)gw * DMODEL;
        __half* xo = g_xh + (size_t)gw * DMODEL;
        float lg[NEXP], ln[NEXP];
#pragma unroll
        for (int e = 0; e < NEXP; e++) { lg[e] = 0.f; ln[e] = 0.f; }
        for (int d = lane; d < DMODEL; d += 32) {
            float xv = xr[d];
            xo[d] = __float2half_rn(xv);        // fused fp16 quantization of x
#pragma unroll
            for (int e = 0; e < NEXP; e++) {
                lg[e] += xv * Wg[d * NEXP + e];
                ln[e] += xv * Wn[d * NEXP + e];
            }
        }
#pragma unroll
        for (int o = 16; o > 0; o >>= 1) {
#pragma unroll
            for (int e = 0; e < NEXP; e++) {
                lg[e] += __shfl_xor_sync(0xffffffffu, lg[e], o);
                ln[e] += __shfl_xor_sync(0xffffffffu, ln[e], o);
            }
        }
        if (lane == 0) {
            float nv[NEXP];
#pragma unroll
            for (int e = 0; e < NEXP; e++) {
                float nl = ln[e] + bn[e];
                float sp = (nl > 20.f) ? nl : log1pf(expf(nl));
                nv[e] = lg[e] + bg[e] + noise[gw * NEXP + e] * sp;
            }
            int i0 = 0;
#pragma unroll
            for (int e = 1; e < NEXP; e++) if (nv[e] > nv[i0]) i0 = e;
            int i1 = (i0 == 0) ? 1 : 0;
#pragma unroll
            for (int e = 0; e < NEXP; e++) if (e != i0 && nv[e] > nv[i1]) i1 = e;
            float e1 = expf(nv[i1] - nv[i0]);
            float s = 1.f + e1;
            g_topi[gw * 2]     = i0;  g_topg[gw * 2]     = 1.f / s;
            g_topi[gw * 2 + 1] = i1;  g_topg[gw * 2 + 1] = e1 / s;
            atomicAdd(&g_counts[i0], 1);
            atomicAdd(&g_counts[i1], 1);
        }
    }
    __syncthreads();
    if (threadIdx.x == 0) {
        __threadfence();
        int prev = atomicAdd(&g_done, 1);
        if (prev == (int)gridDim.x - 1) {
            g_done = 0;
            __threadfence();
            int acc = 0;
            for (int e = 0; e < NEXP; e++) {
                g_off[e] = acc; g_cursor[e] = acc;
                acc += g_counts[e];
                g_counts[e] = 0;        // ready for next replay
            }
            g_off[NEXP] = acc;
        }
    }
}

__global__ void scatter_kernel() {
    int t = blockIdx.x * blockDim.x + threadIdx.x;
    if (t >= T_TOKENS) return;
#pragma unroll
    for (int k = 0; k < TOPK; k++) {
        int e = g_topi[t * 2 + k];
        int pos = atomicAdd(&g_cursor[e], 1);
        g_tok[pos]  = t;
        g_gate[pos] = g_topg[t * 2 + k];
        g_pos[t * 2 + k] = pos;
    }
}

// out[t] = g_o[slot0] + g_o[slot1]
__global__ void combine_kernel(float4* __restrict__ out) {
    int idx = blockIdx.x * blockDim.x + threadIdx.x;
    int t  = idx >> 8;
    int d4 = idx & 255;
    const float4* r0 = (const float4*)(g_o + (size_t)g_pos[t * 2]     * DMODEL) + d4;
    const float4* r1 = (const float4*)(g_o + (size_t)g_pos[t * 2 + 1] * DMODEL) + d4;
    float4 a = *r0, b = *r1;
    a.x += b.x; a.y += b.y; a.z += b.z; a.w += b.w;
    out[idx] = a;
}

// ---------------------------------------------------------------------------
// Grouped GEMM: mma.sync.m16n8k16 fp16 (f32 accum), all-ldmatrix operands.
//   4 warps, warp tile 64x64, CTA tile 128x128x64, NSTG=3 cp.async ring.
//   PHASE 0: g_hh = fp16(relu(gather(g_xh) @ W1h + b1))   K=1024 (16 iters)
//   PHASE 1: g_o[slot] = gate * (g_hh @ W2h + b2)         K=4096 (64 iters)
#define BM 128
#define BN 128
#define BK 64
#define NSTG 3
#define A_BYTES   (BM * 128)                  // 16384: 128 rows x 64 halves (128B, XOR swizzle)
#define B_BYTES   (BK * 256)                  // 16384: 64 k-rows x 128 halves (256B, XOR swizzle)
#define STG_BYTES (A_BYTES + B_BYTES)         // 32768
#define SMEM_BIAS (NSTG * STG_BYTES)
#define SMEM_TOTAL (SMEM_BIAS + BN * 4)       // 98816 -> 2 CTAs/SM

__device__ __forceinline__ void mma_f16(float* c, const uint32_t* a, const uint32_t* b) {
    asm volatile(
        "mma.sync.aligned.m16n8k16.row.col.f32.f16.f16.f32 "
        "{%0,%1,%2,%3}, {%4,%5,%6,%7}, {%8,%9}, {%0,%1,%2,%3};"
        : "+f"(c[0]), "+f"(c[1]), "+f"(c[2]), "+f"(c[3])
        : "r"(a[0]), "r"(a[1]), "r"(a[2]), "r"(a[3]), "r"(b[0]), "r"(b[1]));
}
__device__ __forceinline__ void ldsm_x4(uint32_t* r, uint32_t addr) {
    asm volatile("ldmatrix.sync.aligned.m8n8.x4.shared.b16 {%0,%1,%2,%3}, [%4];"
                 : "=r"(r[0]), "=r"(r[1]), "=r"(r[2]), "=r"(r[3]) : "r"(addr));
}
__device__ __forceinline__ void ldsm_x4_t(uint32_t* r, uint32_t addr) {
    asm volatile("ldmatrix.sync.aligned.m8n8.x4.trans.shared.b16 {%0,%1,%2,%3}, [%4];"
                 : "=r"(r[0]), "=r"(r[1]), "=r"(r[2]), "=r"(r[3]) : "r"(addr));
}

template <int PHASE>
__global__ __launch_bounds__(128, 2)
void moe_gemm_mma(const float* __restrict__ b1, const float* __restrict__ b2) {
    constexpr int K  = PHASE ? DFFN : DMODEL;
    constexpr int NN = PHASE ? DMODEL : DFFN;

    int e  = blockIdx.x >> 5;
    int mt = blockIdx.x & (MT_MAX - 1);
    int off0  = g_off[e];
    int count = g_off[e + 1] - off0;
    if (mt * BM >= count) return;
    int n0 = blockIdx.y * BN;

    extern __shared__ char smem[];
    uint32_t sb = smem_u32(smem);
    float* sBias = (float*)(smem + SMEM_BIAS);

    int tid  = threadIdx.x;
    int wid  = tid >> 5;
    int lane = tid & 31;
    int wm = wid & 1;              // 2 warps along M (64 rows)
    int wn = wid >> 1;             // 2 warps along N (64 cols)

    const float* bias = PHASE ? (b2 + e * DMODEL) : (b1 + e * DFFN);
    sBias[tid] = bias[n0 + tid];   // blockDim == BN == 128

    const __half* Bsrc = PHASE ? (g_w2h + (size_t)e * DFFN * DMODEL)
                               : (g_w1h + (size_t)e * DMODEL * DFFN);

    // ---- per-thread cp.async assignments (128 threads) ----
    int ac = tid & 7;
    const __half* aP[8];
    uint32_t aDst[8];
#pragma unroll
    for (int i = 0; i < 8; i++) {
        int idx = tid + i * 128;
        int row = idx >> 3;
        int lr = mt * BM + row;
        if (lr >= count) lr = count - 1;
        int slot = off0 + lr;
        const __half* base = PHASE ? (g_hh + (size_t)slot * DFFN)
                                   : (g_xh + (size_t)g_tok[slot] * DMODEL);
        aP[i]  = base + ac * 8;
        aDst[i] = (uint32_t)(row * 128 + ((ac ^ (row & 7)) << 4));
    }

    const int nIter = K / BK;

    auto prefetch = [&](int s, int k0) {
        uint32_t ab = sb + s * STG_BYTES;
        uint32_t bb = ab + A_BYTES;
#pragma unroll
        for (int i = 0; i < 8; i++)
            cp_async16u(ab + aDst[i], aP[i] + k0);
#pragma unroll
        for (int i = 0; i < 8; i++) {   // B: 64 k-rows x 16 chunks(16B=8 halves)
            int idx = tid + i * 128;
            int kr = idx >> 4, cn = idx & 15;
            cp_async16u(bb + (uint32_t)(kr * 256 + ((cn ^ (kr & 7)) << 4)),
                        Bsrc + (size_t)(k0 + kr) * NN + n0 + cn * 8);
        }
    };

#pragma unroll
    for (int p = 0; p < NSTG; p++) { prefetch(p, p * BK); CP_COMMIT(); }

    float acc[4][8][4];
#pragma unroll
    for (int mi = 0; mi < 4; mi++)
#pragma unroll
        for (int nj = 0; nj < 8; nj++)
#pragma unroll
            for (int r = 0; r < 4; r++) acc[mi][nj][r] = 0.f;

    int lrow = (lane & 7) + (((lane >> 3) & 1) << 3);   // 0..15
    int lhi  = lane >> 4;                                // 0/1

    for (int i = 0; i < nIter; i++) {
        int rem = nIter - 1 - i;
        if (rem >= NSTG - 1)      asm volatile("cp.async.wait_group 2;\n" ::: "memory");
        else if (rem == 1)        asm volatile("cp.async.wait_group 1;\n" ::: "memory");
        else                      asm volatile("cp.async.wait_group 0;\n" ::: "memory");
        __syncthreads();
        int s = i % NSTG;
        uint32_t aBase = sb + s * STG_BYTES;
        uint32_t bBase = aBase + A_BYTES;

#pragma unroll
        for (int ks = 0; ks < 4; ks++) {       // 4 x k16
            uint32_t ra[4][4];
#pragma unroll
            for (int mi = 0; mi < 4; mi++) {
                int row = wm * 64 + mi * 16 + lrow;
                int chunk = 2 * ks + lhi;
                uint32_t addr = aBase + (uint32_t)(row * 128 + ((chunk ^ (row & 7)) << 4));
                ldsm_x4(ra[mi], addr);
            }
            uint32_t rbq[4][4];
#pragma unroll
            for (int nb = 0; nb < 4; nb++) {
                int kr = ks * 16 + lrow;
                int cn = wn * 8 + nb * 2 + lhi;
                uint32_t addr = bBase + (uint32_t)(kr * 256 + ((cn ^ (kr & 7)) << 4));
                ldsm_x4_t(rbq[nb], addr);
            }
#pragma unroll
            for (int mi = 0; mi < 4; mi++)
#pragma unroll
                for (int nj = 0; nj < 8; nj++)
                    mma_f16(acc[mi][nj], ra[mi], &rbq[nj >> 1][(nj & 1) * 2]);
        }
        __syncthreads();
        if (i + NSTG < nIter) { prefetch(s, (i + NSTG) * BK); CP_COMMIT(); }
    }

    // ---- epilogue straight from registers ----
    int g  = lane >> 2;
    int tg = lane & 3;
#pragma unroll
    for (int mi = 0; mi < 4; mi++) {
#pragma unroll
        for (int half = 0; half < 2; half++) {
            int lr = mt * BM + wm * 64 + mi * 16 + half * 8 + g;
            if (lr >= count) continue;
            int slot = off0 + lr;
            if (PHASE == 0) {
                __half* hrow = g_hh + (size_t)slot * DFFN + n0;
#pragma unroll
                for (int nj = 0; nj < 8; nj++) {
                    int cl = wn * 64 + nj * 8 + tg * 2;
                    float vx = fmaxf(acc[mi][nj][half * 2 + 0] + sBias[cl],     0.f);
                    float vy = fmaxf(acc[mi][nj][half * 2 + 1] + sBias[cl + 1], 0.f);
                    __half2 h = __float22half2_rn(make_float2(vx, vy));
                    *reinterpret_cast<uint32_t*>(hrow + cl) = *reinterpret_cast<uint32_t*>(&h);
                }
            } else {
                float gate = g_gate[slot];
                float* orow = g_o + (size_t)slot * DMODEL + n0;
#pragma unroll
                for (int nj = 0; nj < 8; nj++) {
                    int cl = wn * 64 + nj * 8 + tg * 2;
                    float2 v;
                    v.x = (acc[mi][nj][half * 2 + 0] + sBias[cl])     * gate;
                    v.y = (acc[mi][nj][half * 2 + 1] + sBias[cl + 1]) * gate;
                    *(float2*)(orow + cl) = v;
                }
            }
        }
    }
}

// ---------------------------------------------------------------------------
extern "C" void kernel_launch(void* const* d_in, const int* in_sizes, int n_in,
                              void* d_out, int out_size) {
    const float* x     = (const float*)d_in[0];
    const float* noise = (const float*)d_in[1];
    const float* Wg    = (const float*)d_in[2];
    const float* bg    = (const float*)d_in[3];
    const float* Wn    = (const float*)d_in[4];
    const float* bn    = (const float*)d_in[5];
    const float* W1    = (const float*)d_in[6];
    const float* b1    = (const float*)d_in[7];
    const float* W2    = (const float*)d_in[8];
    const float* b2    = (const float*)d_in[9];
    float* out = (float*)d_out;

    __half *w1h_ptr, *w2h_ptr;
    cudaGetSymbolAddress((void**)&w1h_ptr, g_w1h);
    cudaGetSymbolAddress((void**)&w2h_ptr, g_w2h);

    cudaFuncSetAttribute(moe_gemm_mma<0>, cudaFuncAttributeMaxDynamicSharedMemorySize, SMEM_TOTAL);
    cudaFuncSetAttribute(moe_gemm_mma<1>, cudaFuncAttributeMaxDynamicSharedMemorySize, SMEM_TOTAL);

    // Fork a side stream for weight conversion (overlaps router/scatter and fc1).
    // kernel_launch runs only a handful of times (correctness + capture); fresh
    // stream/event creation per call is host-side only and capture-legal.
    cudaStream_t s2;
    cudaStreamCreateWithFlags(&s2, cudaStreamNonBlocking);
    cudaEvent_t evFork, evW1, evW2;
    cudaEventCreateWithFlags(&evFork, cudaEventDisableTiming);
    cudaEventCreateWithFlags(&evW1,  cudaEventDisableTiming);
    cudaEventCreateWithFlags(&evW2,  cudaEventDisableTiming);

    cudaEventRecord(evFork, 0);
    cudaStreamWaitEvent(s2, evFork, 0);
    convert_w<<<2048, 256, 0, s2>>>((const float4*)W1, (uint2*)w1h_ptr);
    cudaEventRecord(evW1, s2);
    convert_w<<<2048, 256, 0, s2>>>((const float4*)W2, (uint2*)w2h_ptr);
    cudaEventRecord(evW2, s2);

    router_kernel<<<(T_TOKENS * 32) / 256, 256>>>(x, noise, Wg, bg, Wn, bn);   // legacy
    scatter_kernel<<<T_TOKENS / 256, 256>>>();

    cudaStreamWaitEvent(0, evW1, 0);       // fc1 needs W1h
    moe_gemm_mma<0><<<dim3(NEXP * MT_MAX, DFFN / BN), 128, SMEM_TOTAL>>>(b1, b2);
    cudaStreamWaitEvent(0, evW2, 0);       // fc2 needs W2h (already done under fc1)
    moe_gemm_mma<1><<<dim3(NEXP * MT_MAX, DMODEL / BN), 128, SMEM_TOTAL>>>(b1, b2);
    combine_kernel<<<(T_TOKENS * 256) / 256, 256>>>((float4*)out);
}

// round 15
// speedup vs baseline: 1.9196x; 1.0112x over previous
#include <cuda_runtime.h>
#include <cuda_fp16.h>
#include <math.h>
#include <cstdint>
#include <stdint.h>

#define T_TOKENS 4096
#define DMODEL   1024
#define DFFN     4096
#define NEXP     8
#define TOPK     2
#define NSLOTS   (T_TOKENS * TOPK)
#define MT_MAX   32

// ---- scratch (__device__ globals; allocation-free rule) ----
__device__ __half g_hh[(size_t)NSLOTS * DFFN];        // 64 MiB fp16 activations
__device__ __half g_xh[(size_t)T_TOKENS * DMODEL];    // 8 MiB  fp16 x
__device__ __half g_w1h[(size_t)NEXP * DMODEL * DFFN];// 64 MiB fp16 W1
__device__ __half g_w2h[(size_t)NEXP * DFFN * DMODEL];// 64 MiB fp16 W2
__device__ float  g_o[(size_t)NSLOTS * DMODEL];       // 32 MiB per-slot fc2 output
__device__ int    g_tok[NSLOTS];
__device__ float  g_gate[NSLOTS];
__device__ int    g_pos[T_TOKENS * TOPK];
__device__ int    g_counts[NEXP];
__device__ int    g_cursor[NEXP];
__device__ int    g_off[NEXP + 1];
__device__ int    g_topi[T_TOKENS * TOPK];
__device__ float  g_topg[T_TOKENS * TOPK];
__device__ int    g_done;

// ---------------------------------------------------------------------------
__device__ __forceinline__ uint32_t smem_u32(const void* p) {
    uint32_t a;
    asm("{ .reg .u64 t; cvta.to.shared.u64 t, %1; cvt.u32.u64 %0, t; }" : "=r"(a) : "l"(p));
    return a;
}
__device__ __forceinline__ void cp_async16u(uint32_t daddr, const void* src) {
    asm volatile("cp.async.cg.shared.global [%0], [%1], 16;\n" :: "r"(daddr), "l"(src));
}
#define CP_COMMIT() asm volatile("cp.async.commit_group;\n" ::: "memory")

// ---------------------------------------------------------------------------
// W (f32) -> fp16 scratch, one weight tensor per launch
#define W_F4 8388608      // NEXP*DMODEL*DFFN / 4
__global__ void convert_w(const float4* __restrict__ W, uint2* __restrict__ dst) {
    int stride = gridDim.x * blockDim.x;
    for (int i = blockIdx.x * blockDim.x + threadIdx.x; i < W_F4; i += stride) {
        float4 v = W[i];
        __half2 h0 = __float22half2_rn(make_float2(v.x, v.y));
        __half2 h1 = __float22half2_rn(make_float2(v.z, v.w));
        uint2 u;
        u.x = *reinterpret_cast<uint32_t*>(&h0);
        u.y = *reinterpret_cast<uint32_t*>(&h1);
        dst[i] = u;
    }
}

// One warp per token: noisy top-2 router. Also writes fp16 x to g_xh.
// Last block computes expert offsets.
__global__ void router_kernel(const float* __restrict__ x, const float* __restrict__ noise,
                              const float* __restrict__ Wg, const float* __restrict__ bg,
                              const float* __restrict__ Wn, const float* __restrict__ bn) {
    int gw = (blockIdx.x * blockDim.x + threadIdx.x) >> 5;
    int lane = threadIdx.x & 31;
    if (gw < T_TOKENS) {
        const float* xr = x + (size_t)gw * DMODEL;
        __half* xo = g_xh + (size_t)gw * DMODEL;
        float lg[NEXP], ln[NEXP];
#pragma unroll
        for (int e = 0; e < NEXP; e++) { lg[e] = 0.f; ln[e] = 0.f; }
        for (int d = lane; d < DMODEL; d += 32) {
            float xv = xr[d];
            xo[d] = __float2half_rn(xv);        // fused fp16 quantization of x
#pragma unroll
            for (int e = 0; e < NEXP; e++) {
                lg[e] += xv * Wg[d * NEXP + e];
                ln[e] += xv * Wn[d * NEXP + e];
            }
        }
#pragma unroll
        for (int o = 16; o > 0; o >>= 1) {
#pragma unroll
            for (int e = 0; e < NEXP; e++) {
                lg[e] += __shfl_xor_sync(0xffffffffu, lg[e], o);
                ln[e] += __shfl_xor_sync(0xffffffffu, ln[e], o);
            }
        }
        if (lane == 0) {
            float nv[NEXP];
#pragma unroll
            for (int e = 0; e < NEXP; e++) {
                float nl = ln[e] + bn[e];
                float sp = (nl > 20.f) ? nl : log1pf(expf(nl));
                nv[e] = lg[e] + bg[e] + noise[gw * NEXP + e] * sp;
            }
            int i0 = 0;
#pragma unroll
            for (int e = 1; e < NEXP; e++) if (nv[e] > nv[i0]) i0 = e;
            int i1 = (i0 == 0) ? 1 : 0;
#pragma unroll
            for (int e = 0; e < NEXP; e++) if (e != i0 && nv[e] > nv[i1]) i1 = e;
            float e1 = expf(nv[i1] - nv[i0]);
            float s = 1.f + e1;
            g_topi[gw * 2]     = i0;  g_topg[gw * 2]     = 1.f / s;
            g_topi[gw * 2 + 1] = i1;  g_topg[gw * 2 + 1] = e1 / s;
            atomicAdd(&g_counts[i0], 1);
            atomicAdd(&g_counts[i1], 1);
        }
    }
    __syncthreads();
    if (threadIdx.x == 0) {
        __threadfence();
        int prev = atomicAdd(&g_done, 1);
        if (prev == (int)gridDim.x - 1) {
            g_done = 0;
            __threadfence();
            int acc = 0;
            for (int e = 0; e < NEXP; e++) {
                g_off[e] = acc; g_cursor[e] = acc;
                acc += g_counts[e];
                g_counts[e] = 0;        // ready for next replay
            }
            g_off[NEXP] = acc;
        }
    }
}

__global__ void scatter_kernel() {
    int t = blockIdx.x * blockDim.x + threadIdx.x;
    if (t >= T_TOKENS) return;
#pragma unroll
    for (int k = 0; k < TOPK; k++) {
        int e = g_topi[t * 2 + k];
        int pos = atomicAdd(&g_cursor[e], 1);
        g_tok[pos]  = t;
        g_gate[pos] = g_topg[t * 2 + k];
        g_pos[t * 2 + k] = pos;
    }
}

// out[t] = g_o[slot0] + g_o[slot1]
__global__ void combine_kernel(float4* __restrict__ out) {
    int idx = blockIdx.x * blockDim.x + threadIdx.x;
    int t  = idx >> 8;
    int d4 = idx & 255;
    const float4* r0 = (const float4*)(g_o + (size_t)g_pos[t * 2]     * DMODEL) + d4;
    const float4* r1 = (const float4*)(g_o + (size_t)g_pos[t * 2 + 1] * DMODEL) + d4;
    float4 a = *r0, b = *r1;
    a.x += b.x; a.y += b.y; a.z += b.z; a.w += b.w;
    out[idx] = a;
}

// ---------------------------------------------------------------------------
// Grouped GEMM: mma.sync.m16n8k16 fp16 (f32 accum), all-ldmatrix operands.
//   4 warps, warp tile 64x64, CTA tile 128x128x64, NSTG=3 cp.async ring.
//   Grid: x = N-tile (fastest -> co-resident CTAs share the A tile via L2),
//         y = expert*MT + m-tile (same-expert groups share the whole W slab).
//   PHASE 0: g_hh = fp16(relu(gather(g_xh) @ W1h + b1))   K=1024 (16 iters)
//   PHASE 1: g_o[slot] = gate * (g_hh @ W2h + b2)         K=4096 (64 iters)
#define BM 128
#define BN 128
#define BK 64
#define NSTG 3
#define A_BYTES   (BM * 128)                  // 16384: 128 rows x 64 halves (128B, XOR swizzle)
#define B_BYTES   (BK * 256)                  // 16384: 64 k-rows x 128 halves (256B, XOR swizzle)
#define STG_BYTES (A_BYTES + B_BYTES)         // 32768
#define SMEM_BIAS (NSTG * STG_BYTES)
#define SMEM_TOTAL (SMEM_BIAS + BN * 4)       // 98816 -> 2 CTAs/SM

__device__ __forceinline__ void mma_f16(float* c, const uint32_t* a, const uint32_t* b) {
    asm volatile(
        "mma.sync.aligned.m16n8k16.row.col.f32.f16.f16.f32 "
        "{%0,%1,%2,%3}, {%4,%5,%6,%7}, {%8,%9}, {%0,%1,%2,%3};"
        : "+f"(c[0]), "+f"(c[1]), "+f"(c[2]), "+f"(c[3])
        : "r"(a[0]), "r"(a[1]), "r"(a[2]), "r"(a[3]), "r"(b[0]), "r"(b[1]));
}
__device__ __forceinline__ void ldsm_x4(uint32_t* r, uint32_t addr) {
    asm volatile("ldmatrix.sync.aligned.m8n8.x4.shared.b16 {%0,%1,%2,%3}, [%4];"
                 : "=r"(r[0]), "=r"(r[1]), "=r"(r[2]), "=r"(r[3]) : "r"(addr));
}
__device__ __forceinline__ void ldsm_x4_t(uint32_t* r, uint32_t addr) {
    asm volatile("ldmatrix.sync.aligned.m8n8.x4.trans.shared.b16 {%0,%1,%2,%3}, [%4];"
                 : "=r"(r[0]), "=r"(r[1]), "=r"(r[2]), "=r"(r[3]) : "r"(addr));
}

template <int PHASE>
__global__ __launch_bounds__(128, 2)
void moe_gemm_mma(const float* __restrict__ b1, const float* __restrict__ b2) {
    constexpr int K  = PHASE ? DFFN : DMODEL;
    constexpr int NN = PHASE ? DMODEL : DFFN;

    int gm = blockIdx.y;                 // expert*MT + m-tile
    int e  = gm >> 5;
    int mt = gm & (MT_MAX - 1);
    int off0  = g_off[e];
    int count = g_off[e + 1] - off0;
    if (mt * BM >= count) return;
    int n0 = blockIdx.x * BN;            // N-tile fastest

    extern __shared__ char smem[];
    uint32_t sb = smem_u32(smem);
    float* sBias = (float*)(smem + SMEM_BIAS);

    int tid  = threadIdx.x;
    int wid  = tid >> 5;
    int lane = tid & 31;
    int wm = wid & 1;              // 2 warps along M (64 rows)
    int wn = wid >> 1;             // 2 warps along N (64 cols)

    const float* bias = PHASE ? (b2 + e * DMODEL) : (b1 + e * DFFN);
    sBias[tid] = bias[n0 + tid];   // blockDim == BN == 128

    const __half* Bsrc = PHASE ? (g_w2h + (size_t)e * DFFN * DMODEL)
                               : (g_w1h + (size_t)e * DMODEL * DFFN);

    // ---- per-thread cp.async assignments (128 threads) ----
    int ac = tid & 7;
    const __half* aP[8];
    uint32_t aDst[8];
#pragma unroll
    for (int i = 0; i < 8; i++) {
        int idx = tid + i * 128;
        int row = idx >> 3;
        int lr = mt * BM + row;
        if (lr >= count) lr = count - 1;
        int slot = off0 + lr;
        const __half* base = PHASE ? (g_hh + (size_t)slot * DFFN)
                                   : (g_xh + (size_t)g_tok[slot] * DMODEL);
        aP[i]  = base + ac * 8;
        aDst[i] = (uint32_t)(row * 128 + ((ac ^ (row & 7)) << 4));
    }

    const int nIter = K / BK;

    auto prefetch = [&](int s, int k0) {
        uint32_t ab = sb + s * STG_BYTES;
        uint32_t bb = ab + A_BYTES;
#pragma unroll
        for (int i = 0; i < 8; i++)
            cp_async16u(ab + aDst[i], aP[i] + k0);
#pragma unroll
        for (int i = 0; i < 8; i++) {   // B: 64 k-rows x 16 chunks(16B=8 halves)
            int idx = tid + i * 128;
            int kr = idx >> 4, cn = idx & 15;
            cp_async16u(bb + (uint32_t)(kr * 256 + ((cn ^ (kr & 7)) << 4)),
                        Bsrc + (size_t)(k0 + kr) * NN + n0 + cn * 8);
        }
    };

#pragma unroll
    for (int p = 0; p < NSTG; p++) { prefetch(p, p * BK); CP_COMMIT(); }

    float acc[4][8][4];
#pragma unroll
    for (int mi = 0; mi < 4; mi++)
#pragma unroll
        for (int nj = 0; nj < 8; nj++)
#pragma unroll
            for (int r = 0; r < 4; r++) acc[mi][nj][r] = 0.f;

    int lrow = (lane & 7) + (((lane >> 3) & 1) << 3);   // 0..15
    int lhi  = lane >> 4;                                // 0/1

    for (int i = 0; i < nIter; i++) {
        int rem = nIter - 1 - i;
        if (rem >= NSTG - 1)      asm volatile("cp.async.wait_group 2;\n" ::: "memory");
        else if (rem == 1)        asm volatile("cp.async.wait_group 1;\n" ::: "memory");
        else                      asm volatile("cp.async.wait_group 0;\n" ::: "memory");
        __syncthreads();
        int s = i % NSTG;
        uint32_t aBase = sb + s * STG_BYTES;
        uint32_t bBase = aBase + A_BYTES;

#pragma unroll
        for (int ks = 0; ks < 4; ks++) {       // 4 x k16
            uint32_t ra[4][4];
#pragma unroll
            for (int mi = 0; mi < 4; mi++) {
                int row = wm * 64 + mi * 16 + lrow;
                int chunk = 2 * ks + lhi;
                uint32_t addr = aBase + (uint32_t)(row * 128 + ((chunk ^ (row & 7)) << 4));
                ldsm_x4(ra[mi], addr);
            }
            uint32_t rbq[4][4];
#pragma unroll
            for (int nb = 0; nb < 4; nb++) {
                int kr = ks * 16 + lrow;
                int cn = wn * 8 + nb * 2 + lhi;
                uint32_t addr = bBase + (uint32_t)(kr * 256 + ((cn ^ (kr & 7)) << 4));
                ldsm_x4_t(rbq[nb], addr);
            }
#pragma unroll
            for (int mi = 0; mi < 4; mi++)
#pragma unroll
                for (int nj = 0; nj < 8; nj++)
                    mma_f16(acc[mi][nj], ra[mi], &rbq[nj >> 1][(nj & 1) * 2]);
        }
        __syncthreads();
        if (i + NSTG < nIter) { prefetch(s, (i + NSTG) * BK); CP_COMMIT(); }
    }

    // ---- epilogue straight from registers ----
    int g  = lane >> 2;
    int tg = lane & 3;
#pragma unroll
    for (int mi = 0; mi < 4; mi++) {
#pragma unroll
        for (int half = 0; half < 2; half++) {
            int lr = mt * BM + wm * 64 + mi * 16 + half * 8 + g;
            if (lr >= count) continue;
            int slot = off0 + lr;
            if (PHASE == 0) {
                __half* hrow = g_hh + (size_t)slot * DFFN + n0;
#pragma unroll
                for (int nj = 0; nj < 8; nj++) {
                    int cl = wn * 64 + nj * 8 + tg * 2;
                    float vx = fmaxf(acc[mi][nj][half * 2 + 0] + sBias[cl],     0.f);
                    float vy = fmaxf(acc[mi][nj][half * 2 + 1] + sBias[cl + 1], 0.f);
                    __half2 h = __float22half2_rn(make_float2(vx, vy));
                    *reinterpret_cast<uint32_t*>(hrow + cl) = *reinterpret_cast<uint32_t*>(&h);
                }
            } else {
                float gate = g_gate[slot];
                float* orow = g_o + (size_t)slot * DMODEL + n0;
#pragma unroll
                for (int nj = 0; nj < 8; nj++) {
                    int cl = wn * 64 + nj * 8 + tg * 2;
                    float2 v;
                    v.x = (acc[mi][nj][half * 2 + 0] + sBias[cl])     * gate;
                    v.y = (acc[mi][nj][half * 2 + 1] + sBias[cl + 1]) * gate;
                    *(float2*)(orow + cl) = v;
                }
            }
        }
    }
}

// ---------------------------------------------------------------------------
extern "C" void kernel_launch(void* const* d_in, const int* in_sizes, int n_in,
                              void* d_out, int out_size) {
    const float* x     = (const float*)d_in[0];
    const float* noise = (const float*)d_in[1];
    const float* Wg    = (const float*)d_in[2];
    const float* bg    = (const float*)d_in[3];
    const float* Wn    = (const float*)d_in[4];
    const float* bn    = (const float*)d_in[5];
    const float* W1    = (const float*)d_in[6];
    const float* b1    = (const float*)d_in[7];
    const float* W2    = (const float*)d_in[8];
    const float* b2    = (const float*)d_in[9];
    float* out = (float*)d_out;

    __half *w1h_ptr, *w2h_ptr;
    cudaGetSymbolAddress((void**)&w1h_ptr, g_w1h);
    cudaGetSymbolAddress((void**)&w2h_ptr, g_w2h);

    cudaFuncSetAttribute(moe_gemm_mma<0>, cudaFuncAttributeMaxDynamicSharedMemorySize, SMEM_TOTAL);
    cudaFuncSetAttribute(moe_gemm_mma<1>, cudaFuncAttributeMaxDynamicSharedMemorySize, SMEM_TOTAL);

    // Fork a side stream for weight conversion (overlaps router/scatter and fc1).
    cudaStream_t s2;
    cudaStreamCreateWithFlags(&s2, cudaStreamNonBlocking);
    cudaEvent_t evFork, evW1, evW2;
    cudaEventCreateWithFlags(&evFork, cudaEventDisableTiming);
    cudaEventCreateWithFlags(&evW1,  cudaEventDisableTiming);
    cudaEventCreateWithFlags(&evW2,  cudaEventDisableTiming);

    cudaEventRecord(evFork, 0);
    cudaStreamWaitEvent(s2, evFork, 0);
    convert_w<<<2048, 256, 0, s2>>>((const float4*)W1, (uint2*)w1h_ptr);
    cudaEventRecord(evW1, s2);
    convert_w<<<2048, 256, 0, s2>>>((const float4*)W2, (uint2*)w2h_ptr);
    cudaEventRecord(evW2, s2);

    router_kernel<<<(T_TOKENS * 32) / 256, 256>>>(x, noise, Wg, bg, Wn, bn);
    scatter_kernel<<<T_TOKENS / 256, 256>>>();

    cudaStreamWaitEvent(0, evW1, 0);       // fc1 needs W1h
    moe_gemm_mma<0><<<dim3(DFFN / BN, NEXP * MT_MAX), 128, SMEM_TOTAL>>>(b1, b2);
    cudaStreamWaitEvent(0, evW2, 0);       // fc2 needs W2h (already done under fc1)
    moe_gemm_mma<1><<<dim3(DMODEL / BN, NEXP * MT_MAX), 128, SMEM_TOTAL>>>(b1, b2);
    combine_kernel<<<(T_TOKENS * 256) / 256, 256>>>((float4*)out);
}

// round 17
// speedup vs baseline: 1.9245x; 1.0026x over previous
#include <cuda_runtime.h>
#include <cuda_fp16.h>
#include <math.h>
#include <cstdint>
#include <stdint.h>

#define T_TOKENS 4096
#define DMODEL   1024
#define DFFN     4096
#define NEXP     8
#define TOPK     2
#define NSLOTS   (T_TOKENS * TOPK)
#define MT_MAX   32

// ---- scratch (__device__ globals; allocation-free rule) ----
__device__ __half g_hh[(size_t)NSLOTS * DFFN];        // 64 MiB fp16 activations
__device__ __half g_xh[(size_t)T_TOKENS * DMODEL];    // 8 MiB  fp16 x
__device__ __half g_w1h[(size_t)NEXP * DMODEL * DFFN];// 64 MiB fp16 W1
__device__ __half g_w2h[(size_t)NEXP * DFFN * DMODEL];// 64 MiB fp16 W2
__device__ float  g_o[(size_t)NSLOTS * DMODEL];       // 32 MiB per-slot fc2 output
__device__ int    g_tok[NSLOTS];
__device__ float  g_gate[NSLOTS];
__device__ int    g_pos[T_TOKENS * TOPK];
__device__ int    g_counts[NEXP];
__device__ int    g_cursor[NEXP];
__device__ int    g_off[NEXP + 1];
__device__ int    g_topi[T_TOKENS * TOPK];
__device__ float  g_topg[T_TOKENS * TOPK];
__device__ int    g_done;

// ---------------------------------------------------------------------------
__device__ __forceinline__ uint32_t smem_u32(const void* p) {
    uint32_t a;
    asm("{ .reg .u64 t; cvta.to.shared.u64 t, %1; cvt.u32.u64 %0, t; }" : "=r"(a) : "l"(p));
    return a;
}
__device__ __forceinline__ void cp_async16u(uint32_t daddr, const void* src) {
    asm volatile("cp.async.cg.shared.global [%0], [%1], 16;\n" :: "r"(daddr), "l"(src));
}
#define CP_COMMIT() asm volatile("cp.async.commit_group;\n" ::: "memory")

// ---------------------------------------------------------------------------
// W (f32) -> fp16 scratch, one weight tensor per launch
#define W_F4 8388608      // NEXP*DMODEL*DFFN / 4
__global__ void convert_w(const float4* __restrict__ W, uint2* __restrict__ dst) {
    int stride = gridDim.x * blockDim.x;
    for (int i = blockIdx.x * blockDim.x + threadIdx.x; i < W_F4; i += stride) {
        float4 v = W[i];
        __half2 h0 = __float22half2_rn(make_float2(v.x, v.y));
        __half2 h1 = __float22half2_rn(make_float2(v.z, v.w));
        uint2 u;
        u.x = *reinterpret_cast<uint32_t*>(&h0);
        u.y = *reinterpret_cast<uint32_t*>(&h1);
        dst[i] = u;
    }
}

// One warp per token: noisy top-2 router. Also writes fp16 x to g_xh.
// Last block computes expert offsets.
__global__ void router_kernel(const float* __restrict__ x, const float* __restrict__ noise,
                              const float* __restrict__ Wg, const float* __restrict__ bg,
                              const float* __restrict__ Wn, const float* __restrict__ bn) {
    int gw = (blockIdx.x * blockDim.x + threadIdx.x) >> 5;
    int lane = threadIdx.x & 31;
    if (gw < T_TOKENS) {
        const float* xr = x + (size_t)gw * DMODEL;
        __half* xo = g_xh + (size_t)gw * DMODEL;
        float lg[NEXP], ln[NEXP];
#pragma unroll
        for (int e = 0; e < NEXP; e++) { lg[e] = 0.f; ln[e] = 0.f; }
        for (int d = lane; d < DMODEL; d += 32) {
            float xv = xr[d];
            xo[d] = __float2half_rn(xv);        // fused fp16 quantization of x
#pragma unroll
            for (int e = 0; e < NEXP; e++) {
                lg[e] += xv * Wg[d * NEXP + e];
                ln[e] += xv * Wn[d * NEXP + e];
            }
        }
#pragma unroll
        for (int o = 16; o > 0; o >>= 1) {
#pragma unroll
            for (int e = 0; e < NEXP; e++) {
                lg[e] += __shfl_xor_sync(0xffffffffu, lg[e], o);
                ln[e] += __shfl_xor_sync(0xffffffffu, ln[e], o);
            }
        }
        if (lane == 0) {
            float nv[NEXP];
#pragma unroll
            for (int e = 0; e < NEXP; e++) {
                float nl = ln[e] + bn[e];
                float sp = (nl > 20.f) ? nl : log1pf(expf(nl));
                nv[e] = lg[e] + bg[e] + noise[gw * NEXP + e] * sp;
            }
            int i0 = 0;
#pragma unroll
            for (int e = 1; e < NEXP; e++) if (nv[e] > nv[i0]) i0 = e;
            int i1 = (i0 == 0) ? 1 : 0;
#pragma unroll
            for (int e = 0; e < NEXP; e++) if (e != i0 && nv[e] > nv[i1]) i1 = e;
            float e1 = expf(nv[i1] - nv[i0]);
            float s = 1.f + e1;
            g_topi[gw * 2]     = i0;  g_topg[gw * 2]     = 1.f / s;
            g_topi[gw * 2 + 1] = i1;  g_topg[gw * 2 + 1] = e1 / s;
            atomicAdd(&g_counts[i0], 1);
            atomicAdd(&g_counts[i1], 1);
        }
    }
    __syncthreads();
    if (threadIdx.x == 0) {
        __threadfence();
        int prev = atomicAdd(&g_done, 1);
        if (prev == (int)gridDim.x - 1) {
            g_done = 0;
            __threadfence();
            int acc = 0;
            for (int e = 0; e < NEXP; e++) {
                g_off[e] = acc; g_cursor[e] = acc;
                acc += g_counts[e];
                g_counts[e] = 0;        // ready for next replay
            }
            g_off[NEXP] = acc;
        }
    }
}

__global__ void scatter_kernel() {
    int t = blockIdx.x * blockDim.x + threadIdx.x;
    if (t >= T_TOKENS) return;
#pragma unroll
    for (int k = 0; k < TOPK; k++) {
        int e = g_topi[t * 2 + k];
        int pos = atomicAdd(&g_cursor[e], 1);
        g_tok[pos]  = t;
        g_gate[pos] = g_topg[t * 2 + k];
        g_pos[t * 2 + k] = pos;
    }
}

// out[t] = g_o[slot0] + g_o[slot1]
__global__ void combine_kernel(float4* __restrict__ out) {
    int idx = blockIdx.x * blockDim.x + threadIdx.x;
    int t  = idx >> 8;
    int d4 = idx & 255;
    const float4* r0 = (const float4*)(g_o + (size_t)g_pos[t * 2]     * DMODEL) + d4;
    const float4* r1 = (const float4*)(g_o + (size_t)g_pos[t * 2 + 1] * DMODEL) + d4;
    float4 a = *r0, b = *r1;
    a.x += b.x; a.y += b.y; a.z += b.z; a.w += b.w;
    out[idx] = a;
}

// ---------------------------------------------------------------------------
// Grouped GEMM: mma.sync.m16n8k16 fp16 (f32 accum), all-ldmatrix operands.
//   4 warps, warp tile 64x64, CTA tile 128x128x64, NSTG=3 cp.async ring.
//   Grid: x = N-tile (fastest), y = expert*MT + m-tile.
//   PHASE 0: g_hh = fp16(relu(gather(g_xh) @ W1h + b1))   K=1024 (16 iters)
//   PHASE 1: g_o[slot] = gate * (g_hh @ W2h + b2)         K=4096 (64 iters)
#define BM 128
#define BN 128
#define BK 64
#define NSTG 3
#define A_BYTES   (BM * 128)
#define B_BYTES   (BK * 256)
#define STG_BYTES (A_BYTES + B_BYTES)         // 32768
#define SMEM_BIAS (NSTG * STG_BYTES)
#define SMEM_TOTAL (SMEM_BIAS + BN * 4)       // 98816 -> 2 CTAs/SM

__device__ __forceinline__ void mma_f16(float* c, const uint32_t* a, const uint32_t* b) {
    asm volatile(
        "mma.sync.aligned.m16n8k16.row.col.f32.f16.f16.f32 "
        "{%0,%1,%2,%3}, {%4,%5,%6,%7}, {%8,%9}, {%0,%1,%2,%3};"
        : "+f"(c[0]), "+f"(c[1]), "+f"(c[2]), "+f"(c[3])
        : "r"(a[0]), "r"(a[1]), "r"(a[2]), "r"(a[3]), "r"(b[0]), "r"(b[1]));
}
__device__ __forceinline__ void ldsm_x4(uint32_t* r, uint32_t addr) {
    asm volatile("ldmatrix.sync.aligned.m8n8.x4.shared.b16 {%0,%1,%2,%3}, [%4];"
                 : "=r"(r[0]), "=r"(r[1]), "=r"(r[2]), "=r"(r[3]) : "r"(addr));
}
__device__ __forceinline__ void ldsm_x4_t(uint32_t* r, uint32_t addr) {
    asm volatile("ldmatrix.sync.aligned.m8n8.x4.trans.shared.b16 {%0,%1,%2,%3}, [%4];"
                 : "=r"(r[0]), "=r"(r[1]), "=r"(r[2]), "=r"(r[3]) : "r"(addr));
}

template <int PHASE>
__global__ __launch_bounds__(128, 2)
void moe_gemm_mma(const float* __restrict__ b1, const float* __restrict__ b2) {
    constexpr int K  = PHASE ? DFFN : DMODEL;
    constexpr int NN = PHASE ? DMODEL : DFFN;

    int gm = blockIdx.y;                 // expert*MT + m-tile
    int e  = gm >> 5;
    int mt = gm & (MT_MAX - 1);
    int off0  = g_off[e];
    int count = g_off[e + 1] - off0;
    if (mt * BM >= count) return;
    int n0 = blockIdx.x * BN;            // N-tile fastest

    extern __shared__ char smem[];
    uint32_t sb = smem_u32(smem);
    float* sBias = (float*)(smem + SMEM_BIAS);

    int tid  = threadIdx.x;
    int wid  = tid >> 5;
    int lane = tid & 31;
    int wm = wid & 1;              // 2 warps along M (64 rows)
    int wn = wid >> 1;             // 2 warps along N (64 cols)

    const float* bias = PHASE ? (b2 + e * DMODEL) : (b1 + e * DFFN);
    sBias[tid] = bias[n0 + tid];   // blockDim == BN == 128

    const __half* Bsrc = PHASE ? (g_w2h + (size_t)e * DFFN * DMODEL)
                               : (g_w1h + (size_t)e * DMODEL * DFFN);

    // ---- per-thread cp.async assignments (128 threads) ----
    int ac = tid & 7;
    const __half* aP[8];
    uint32_t aDst[8];
#pragma unroll
    for (int i = 0; i < 8; i++) {
        int idx = tid + i * 128;
        int row = idx >> 3;
        int lr = mt * BM + row;
        if (lr >= count) lr = count - 1;
        int slot = off0 + lr;
        const __half* base = PHASE ? (g_hh + (size_t)slot * DFFN)
                                   : (g_xh + (size_t)g_tok[slot] * DMODEL);
        aP[i]  = base + ac * 8;
        aDst[i] = (uint32_t)(row * 128 + ((ac ^ (row & 7)) << 4));
    }

    const int nIter = K / BK;

    auto prefetch = [&](int s, int k0) {
        uint32_t ab = sb + s * STG_BYTES;
        uint32_t bb = ab + A_BYTES;
#pragma unroll
        for (int i = 0; i < 8; i++)
            cp_async16u(ab + aDst[i], aP[i] + k0);
#pragma unroll
        for (int i = 0; i < 8; i++) {   // B: 64 k-rows x 16 chunks(16B=8 halves)
            int idx = tid + i * 128;
            int kr = idx >> 4, cn = idx & 15;
            cp_async16u(bb + (uint32_t)(kr * 256 + ((cn ^ (kr & 7)) << 4)),
                        Bsrc + (size_t)(k0 + kr) * NN + n0 + cn * 8);
        }
    };

#pragma unroll
    for (int p = 0; p < NSTG; p++) { prefetch(p, p * BK); CP_COMMIT(); }

    float acc[4][8][4];
#pragma unroll
    for (int mi = 0; mi < 4; mi++)
#pragma unroll
        for (int nj = 0; nj < 8; nj++)
#pragma unroll
            for (int r = 0; r < 4; r++) acc[mi][nj][r] = 0.f;

    int lrow = (lane & 7) + (((lane >> 3) & 1) << 3);   // 0..15
    int lhi  = lane >> 4;                                // 0/1

    for (int i = 0; i < nIter; i++) {
        int rem = nIter - 1 - i;
        if (rem >= NSTG - 1)      asm volatile("cp.async.wait_group 2;\n" ::: "memory");
        else if (rem == 1)        asm volatile("cp.async.wait_group 1;\n" ::: "memory");
        else                      asm volatile("cp.async.wait_group 0;\n" ::: "memory");
        __syncthreads();
        int s = i % NSTG;
        uint32_t aBase = sb + s * STG_BYTES;
        uint32_t bBase = aBase + A_BYTES;

#pragma unroll
        for (int ks = 0; ks < 4; ks++) {       // 4 x k16
            uint32_t ra[4][4];
#pragma unroll
            for (int mi = 0; mi < 4; mi++) {
                int row = wm * 64 + mi * 16 + lrow;
                int chunk = 2 * ks + lhi;
                uint32_t addr = aBase + (uint32_t)(row * 128 + ((chunk ^ (row & 7)) << 4));
                ldsm_x4(ra[mi], addr);
            }
            uint32_t rbq[4][4];
#pragma unroll
            for (int nb = 0; nb < 4; nb++) {
                int kr = ks * 16 + lrow;
                int cn = wn * 8 + nb * 2 + lhi;
                uint32_t addr = bBase + (uint32_t)(kr * 256 + ((cn ^ (kr & 7)) << 4));
                ldsm_x4_t(rbq[nb], addr);
            }
#pragma unroll
            for (int mi = 0; mi < 4; mi++)
#pragma unroll
                for (int nj = 0; nj < 8; nj++)
                    mma_f16(acc[mi][nj], ra[mi], &rbq[nj >> 1][(nj & 1) * 2]);
        }
        __syncthreads();
        if (i + NSTG < nIter) { prefetch(s, (i + NSTG) * BK); CP_COMMIT(); }
    }

    // ---- epilogue straight from registers ----
    int g  = lane >> 2;
    int tg = lane & 3;
#pragma unroll
    for (int mi = 0; mi < 4; mi++) {
#pragma unroll
        for (int half = 0; half < 2; half++) {
            int lr = mt * BM + wm * 64 + mi * 16 + half * 8 + g;
            if (lr >= count) continue;
            int slot = off0 + lr;
            if (PHASE == 0) {
                __half* hrow = g_hh + (size_t)slot * DFFN + n0;
#pragma unroll
                for (int nj = 0; nj < 8; nj++) {
                    int cl = wn * 64 + nj * 8 + tg * 2;
                    float vx = fmaxf(acc[mi][nj][half * 2 + 0] + sBias[cl],     0.f);
                    float vy = fmaxf(acc[mi][nj][half * 2 + 1] + sBias[cl + 1], 0.f);
                    __half2 h = __float22half2_rn(make_float2(vx, vy));
                    *reinterpret_cast<uint32_t*>(hrow + cl) = *reinterpret_cast<uint32_t*>(&h);
                }
            } else {
                float gate = g_gate[slot];
                float* orow = g_o + (size_t)slot * DMODEL + n0;
#pragma unroll
                for (int nj = 0; nj < 8; nj++) {
                    int cl = wn * 64 + nj * 8 + tg * 2;
                    float2 v;
                    v.x = (acc[mi][nj][half * 2 + 0] + sBias[cl])     * gate;
                    v.y = (acc[mi][nj][half * 2 + 1] + sBias[cl + 1]) * gate;
                    *(float2*)(orow + cl) = v;
                }
            }
        }
    }
}

// ---------------------------------------------------------------------------
extern "C" void kernel_launch(void* const* d_in, const int* in_sizes, int n_in,
                              void* d_out, int out_size) {
    const float* x     = (const float*)d_in[0];
    const float* noise = (const float*)d_in[1];
    const float* Wg    = (const float*)d_in[2];
    const float* bg    = (const float*)d_in[3];
    const float* Wn    = (const float*)d_in[4];
    const float* bn    = (const float*)d_in[5];
    const float* W1    = (const float*)d_in[6];
    const float* b1    = (const float*)d_in[7];
    const float* W2    = (const float*)d_in[8];
    const float* b2    = (const float*)d_in[9];
    float* out = (float*)d_out;

    __half *w1h_ptr, *w2h_ptr;
    cudaGetSymbolAddress((void**)&w1h_ptr, g_w1h);
    cudaGetSymbolAddress((void**)&w2h_ptr, g_w2h);

    cudaFuncSetAttribute(moe_gemm_mma<0>, cudaFuncAttributeMaxDynamicSharedMemorySize, SMEM_TOTAL);
    cudaFuncSetAttribute(moe_gemm_mma<1>, cudaFuncAttributeMaxDynamicSharedMemorySize, SMEM_TOTAL);

    // Fork ONE side stream for weight conversion (overlaps router/scatter; W2
    // conversion completes under fc1). Measured-best topology (R15): serial
    // fc1 -> fc2 on the main stream — co-running the two GEMMs thrashes L2
    // and regresses (R16 evidence).
    cudaStream_t s2;
    cudaStreamCreateWithFlags(&s2, cudaStreamNonBlocking);
    cudaEvent_t evFork, evW1, evW2;
    cudaEventCreateWithFlags(&evFork, cudaEventDisableTiming);
    cudaEventCreateWithFlags(&evW1,  cudaEventDisableTiming);
    cudaEventCreateWithFlags(&evW2,  cudaEventDisableTiming);

    cudaEventRecord(evFork, 0);
    cudaStreamWaitEvent(s2, evFork, 0);
    convert_w<<<2048, 256, 0, s2>>>((const float4*)W1, (uint2*)w1h_ptr);
    cudaEventRecord(evW1, s2);
    convert_w<<<2048, 256, 0, s2>>>((const float4*)W2, (uint2*)w2h_ptr);
    cudaEventRecord(evW2, s2);

    router_kernel<<<(T_TOKENS * 32) / 256, 256>>>(x, noise, Wg, bg, Wn, bn);
    scatter_kernel<<<T_TOKENS / 256, 256>>>();

    cudaStreamWaitEvent(0, evW1, 0);       // fc1 needs W1h
    moe_gemm_mma<0><<<dim3(DFFN / BN, NEXP * MT_MAX), 128, SMEM_TOTAL>>>(b1, b2);
    cudaStreamWaitEvent(0, evW2, 0);       // fc2 needs W2h (done under fc1)
    moe_gemm_mma<1><<<dim3(DMODEL / BN, NEXP * MT_MAX), 128, SMEM_TOTAL>>>(b1, b2);
    combine_kernel<<<(T_TOKENS * 256) / 256, 256>>>((float4*)out);

    // Release fork resources so nothing outlives graph teardown (R16 lesson:
    // leftover stream/event objects trip the post-teardown memory check).
    cudaEventDestroy(evFork);
    cudaEventDestroy(evW1);
    cudaEventDestroy(evW2);
    cudaStreamDestroy(s2);
}